// round 6
// baseline (speedup 1.0000x reference)
#include <cuda_runtime.h>
#include <math.h>
#include <stdint.h>

// Problem constants (B=1, H=16, L=1024, D=64)
#define NSEQ 16
#define LSEQ 1024
#define DIM  64
#define D2   128          // feature dim = 2*DIM
#define CHK  64           // chunk length
#define HCHK 32           // half-chunk (K-split for phase 1)
#define NC   (LSEQ/CHK)   // 16 chunks per sequence

// Scratch: two partial buffers (K-split halves); scan combines into A.
__device__ float g_kvA[NSEQ * NC * D2 * DIM];    // 8 MB
__device__ float g_kvB[NSEQ * NC * D2 * DIM];    // 8 MB
__device__ float g_ksumA[NSEQ * NC * D2];        // 128 KB
__device__ float g_ksumB[NSEQ * NC * D2];        // 128 KB

// ---------------------------------------------------------------------------
// tf32 helpers
// ---------------------------------------------------------------------------
__device__ __forceinline__ float f2tf(float x) {
    uint32_t r;
    asm("cvt.rna.tf32.f32 %0, %1;" : "=r"(r) : "f"(x));
    return __uint_as_float(r);
}

__device__ __forceinline__ void mma_tf32(float d[4],
                                         const uint32_t a[4],
                                         const uint32_t b[2],
                                         const float c[4]) {
    asm volatile(
        "mma.sync.aligned.m16n8k8.row.col.f32.tf32.tf32.f32 "
        "{%0,%1,%2,%3}, {%4,%5,%6,%7}, {%8,%9}, {%10,%11,%12,%13};\n"
        : "=f"(d[0]), "=f"(d[1]), "=f"(d[2]), "=f"(d[3])
        : "r"(a[0]), "r"(a[1]), "r"(a[2]), "r"(a[3]),
          "r"(b[0]), "r"(b[1]),
          "f"(c[0]), "f"(c[1]), "f"(c[2]), "f"(c[3]));
}

#define BITS(x) __float_as_uint(x)

// ---------------------------------------------------------------------------
// Kernel 1: per-HALF-chunk KV partial sums via tensor cores.
// grid = NSEQ*NC*2 = 512 blocks, 256 threads (8 warps).
// CTA (s,c,h): C_h[128(d2) x 64(dv)] = k~[h-half]^T @ v[h-half], K=32.
// smem: ks[32][136] (k~ tf32, [j][d2]), vs[32][72]  -> 26.6 KB
// ---------------------------------------------------------------------------
#define K1_KS 136
#define K1_VS 72
#define K1_SMEM ((HCHK*K1_KS + HCHK*K1_VS) * sizeof(float))

__global__ void k_chunksum(const float* __restrict__ kg_,
                           const float* __restrict__ vg_) {
    extern __shared__ float sm[];
    float* ks = sm;                    // [32][136]
    float* vs = sm + HCHK * K1_KS;     // [32][72]

    const int s = blockIdx.x >> 5;
    const int c = (blockIdx.x >> 1) & 15;
    const int h = blockIdx.x & 1;
    const int t = threadIdx.x;

    const int base = s * LSEQ + c * CHK + h * HCHK;
    const float* kg = kg_ + (size_t)base * DIM;
    const float* vg = vg_ + (size_t)base * DIM;

    // Load + feature-map k, load v; tf32-round. 512 float4 over 256 thr.
    for (int i = t; i < HCHK * DIM / 4; i += 256) {
        int j = i >> 4;
        int d = (i & 15) * 4;
        float4 k4 = reinterpret_cast<const float4*>(kg)[i];
        float4 v4 = reinterpret_cast<const float4*>(vg)[i];
        int gl = base - s * LSEQ + j;    // position within sequence
        float w = 1.5707963267948966f * (float)(gl + 1) * (1.0f / (float)LSEQ);
        float sw, cw;
        sincosf(w, &sw, &cw);
        float kx = fmaxf(k4.x, 0.f), ky = fmaxf(k4.y, 0.f);
        float kz = fmaxf(k4.z, 0.f), kw = fmaxf(k4.w, 0.f);
        *reinterpret_cast<float4*>(ks + j * K1_KS + d) =
            make_float4(f2tf(kx * sw), f2tf(ky * sw), f2tf(kz * sw), f2tf(kw * sw));
        *reinterpret_cast<float4*>(ks + j * K1_KS + 64 + d) =
            make_float4(f2tf(kx * cw), f2tf(ky * cw), f2tf(kz * cw), f2tf(kw * cw));
        *reinterpret_cast<float4*>(vs + j * K1_VS + d) =
            make_float4(f2tf(v4.x), f2tf(v4.y), f2tf(v4.z), f2tf(v4.w));
    }
    __syncthreads();

    const int wid  = t >> 5;
    const int lane = t & 31;
    const int g    = lane >> 2;
    const int tig  = lane & 3;
    const int warpM = (wid >> 1) * 32;   // 0,32,64,96 (d2)
    const int warpN = (wid & 1) * 32;    // 0,32 (dv)

    float acc[2][4][4];
#pragma unroll
    for (int mt = 0; mt < 2; mt++)
#pragma unroll
        for (int nt = 0; nt < 4; nt++)
#pragma unroll
            for (int cc = 0; cc < 4; cc++) acc[mt][nt][cc] = 0.f;

#pragma unroll
    for (int kk = 0; kk < 4; kk++) {     // K=32
        const int k0 = kk * 8;
        uint32_t af[2][4];
#pragma unroll
        for (int mt = 0; mt < 2; mt++) {
            int mb = warpM + mt * 16 + g;
            af[mt][0] = BITS(ks[(k0 + tig)     * K1_KS + mb]);
            af[mt][1] = BITS(ks[(k0 + tig)     * K1_KS + mb + 8]);
            af[mt][2] = BITS(ks[(k0 + tig + 4) * K1_KS + mb]);
            af[mt][3] = BITS(ks[(k0 + tig + 4) * K1_KS + mb + 8]);
        }
        uint32_t bf[4][2];
#pragma unroll
        for (int nt = 0; nt < 4; nt++) {
            int nb = warpN + nt * 8 + g;
            bf[nt][0] = BITS(vs[(k0 + tig)     * K1_VS + nb]);
            bf[nt][1] = BITS(vs[(k0 + tig + 4) * K1_VS + nb]);
        }
#pragma unroll
        for (int mt = 0; mt < 2; mt++)
#pragma unroll
            for (int nt = 0; nt < 4; nt++)
                mma_tf32(acc[mt][nt], af[mt], bf[nt], acc[mt][nt]);
    }

    // Store partial chunk KV sum to buffer h.
    float* outp = (h ? g_kvB : g_kvA) + (size_t)(s * NC + c) * D2 * DIM;
#pragma unroll
    for (int mt = 0; mt < 2; mt++)
#pragma unroll
        for (int nt = 0; nt < 4; nt++) {
            int m0 = warpM + mt * 16 + g;
            int n0 = warpN + nt * 8 + 2 * tig;
            *reinterpret_cast<float2*>(outp + m0 * DIM + n0) =
                make_float2(acc[mt][nt][0], acc[mt][nt][1]);
            *reinterpret_cast<float2*>(outp + (m0 + 8) * DIM + n0) =
                make_float2(acc[mt][nt][2], acc[mt][nt][3]);
        }

    // Partial k-sum per feature dim.
    if (t < D2) {
        float ssum = 0.f;
#pragma unroll
        for (int j = 0; j < HCHK; j++) ssum += ks[j * K1_KS + t];
        (h ? g_ksumB : g_ksumA)[(size_t)(s * NC + c) * D2 + t] = ssum;
    }
}

// ---------------------------------------------------------------------------
// Kernel 2: exclusive prefix scan over chunks, combining the two partial
// buffers. Result (exclusive prefix of A+B) written to the A buffers.
// float4-vectorized, 4-chunk MLP batches.
// threads needed: 32768 (kv float4 cols) + 2048 (ksum cols) = 34816
// ---------------------------------------------------------------------------
__global__ void k_scan() {
    const int gtid = blockIdx.x * blockDim.x + threadIdx.x;
    if (gtid < NSEQ * 2048) {
        int s = gtid >> 11;
        int e = gtid & 2047;
        float4* A = reinterpret_cast<float4*>(g_kvA) + (size_t)s * NC * 2048 + e;
        float4* B = reinterpret_cast<float4*>(g_kvB) + (size_t)s * NC * 2048 + e;
        float4 run = make_float4(0.f, 0.f, 0.f, 0.f);
#pragma unroll
        for (int b = 0; b < 4; b++) {
            float4 ta[4], tb[4];
#pragma unroll
            for (int i = 0; i < 4; i++) {
                ta[i] = A[(size_t)(b * 4 + i) * 2048];
                tb[i] = B[(size_t)(b * 4 + i) * 2048];
            }
#pragma unroll
            for (int i = 0; i < 4; i++) {
                A[(size_t)(b * 4 + i) * 2048] = run;
                run.x += ta[i].x + tb[i].x;
                run.y += ta[i].y + tb[i].y;
                run.z += ta[i].z + tb[i].z;
                run.w += ta[i].w + tb[i].w;
            }
        }
    } else if (gtid < NSEQ * 2048 + NSEQ * D2) {
        int idx = gtid - NSEQ * 2048;
        int s = idx >> 7;
        int e = idx & 127;
        float* a = g_ksumA + (size_t)s * NC * D2 + e;
        float* b = g_ksumB + (size_t)s * NC * D2 + e;
        float run = 0.f;
#pragma unroll
        for (int bb = 0; bb < 2; bb++) {
            float ta[8], tb[8];
#pragma unroll
            for (int i = 0; i < 8; i++) {
                ta[i] = a[(bb * 8 + i) * D2];
                tb[i] = b[(bb * 8 + i) * D2];
            }
#pragma unroll
            for (int i = 0; i < 8; i++) {
                a[(bb * 8 + i) * D2] = run;
                run += ta[i] + tb[i];
            }
        }
    }
}

// ---------------------------------------------------------------------------
// Kernel 3: per-chunk output via tensor cores. grid = NSEQ*NC, 256 threads.
// (identical structure to the measured round-3 kernel)
// ---------------------------------------------------------------------------
#define QS3 132
#define US3 132
#define S0S 72
#define VS3 72
#define AS3 68
#define K3_U_FLOATS 9216   /* max(64*132=8448, 128*72=9216) */
#define K3_SMEM_FLOATS (64*QS3 + K3_U_FLOATS + 64*VS3 + 64*AS3 + 128 + 64)
#define K3_SMEM (K3_SMEM_FLOATS * sizeof(float))

__global__ void k_output(const float* __restrict__ qg_,
                         const float* __restrict__ kg_,
                         const float* __restrict__ vg_,
                         float* __restrict__ outg) {
    extern __shared__ float sm[];
    float* qs    = sm;
    float* u     = qs + 64 * QS3;        // k~ then S0
    float* vs    = u + K3_U_FLOATS;
    float* As    = vs + 64 * VS3;
    float* ksum  = As + 64 * AS3;
    float* den   = ksum + 128;

    const int s = blockIdx.x >> 4;
    const int c = blockIdx.x & 15;
    const int t = threadIdx.x;

    const float* qg = qg_ + (size_t)(s * LSEQ + c * CHK) * DIM;
    const float* kg = kg_ + (size_t)(s * LSEQ + c * CHK) * DIM;
    const float* vg = vg_ + (size_t)(s * LSEQ + c * CHK) * DIM;

    for (int i = t; i < CHK * DIM / 4; i += 256) {
        int j = i >> 4;
        int d = (i & 15) * 4;
        float4 q4 = reinterpret_cast<const float4*>(qg)[i];
        float4 k4 = reinterpret_cast<const float4*>(kg)[i];
        float4 v4 = reinterpret_cast<const float4*>(vg)[i];
        int gl = c * CHK + j;
        float w = 1.5707963267948966f * (float)(gl + 1) * (1.0f / (float)LSEQ);
        float sw, cw;
        sincosf(w, &sw, &cw);
        float qx = fmaxf(q4.x, 0.f), qy = fmaxf(q4.y, 0.f);
        float qz = fmaxf(q4.z, 0.f), qw = fmaxf(q4.w, 0.f);
        float kx = fmaxf(k4.x, 0.f), ky = fmaxf(k4.y, 0.f);
        float kz = fmaxf(k4.z, 0.f), kw = fmaxf(k4.w, 0.f);
        *reinterpret_cast<float4*>(qs + j * QS3 + d) =
            make_float4(f2tf(qx * sw), f2tf(qy * sw), f2tf(qz * sw), f2tf(qw * sw));
        *reinterpret_cast<float4*>(qs + j * QS3 + 64 + d) =
            make_float4(f2tf(qx * cw), f2tf(qy * cw), f2tf(qz * cw), f2tf(qw * cw));
        *reinterpret_cast<float4*>(u + j * US3 + d) =
            make_float4(f2tf(kx * sw), f2tf(ky * sw), f2tf(kz * sw), f2tf(kw * sw));
        *reinterpret_cast<float4*>(u + j * US3 + 64 + d) =
            make_float4(f2tf(kx * cw), f2tf(ky * cw), f2tf(kz * cw), f2tf(kw * cw));
        *reinterpret_cast<float4*>(vs + j * VS3 + d) =
            make_float4(f2tf(v4.x), f2tf(v4.y), f2tf(v4.z), f2tf(v4.w));
    }
    if (t < D2) ksum[t] = g_ksumA[(size_t)(s * NC + c) * D2 + t];
    __syncthreads();

    const int wid  = t >> 5;
    const int lane = t & 31;
    const int g    = lane >> 2;
    const int tig  = lane & 3;
    const int warpM = (wid >> 1) * 16;   // 0,16,32,48
    const int warpN = (wid & 1) * 32;    // 0,32

    // ---- Phase A: A = q~ @ k~^T, K=128 ----
    {
        float acc[4][4];
#pragma unroll
        for (int nt = 0; nt < 4; nt++)
#pragma unroll
            for (int cc = 0; cc < 4; cc++) acc[nt][cc] = 0.f;

#pragma unroll
        for (int kk = 0; kk < 16; kk++) {
            const int k0 = kk * 8;
            uint32_t af[4];
            af[0] = BITS(qs[(warpM + g)     * QS3 + k0 + tig]);
            af[1] = BITS(qs[(warpM + g + 8) * QS3 + k0 + tig]);
            af[2] = BITS(qs[(warpM + g)     * QS3 + k0 + tig + 4]);
            af[3] = BITS(qs[(warpM + g + 8) * QS3 + k0 + tig + 4]);
            uint32_t bf[4][2];
#pragma unroll
            for (int nt = 0; nt < 4; nt++) {
                int nb = warpN + nt * 8 + g;
                bf[nt][0] = BITS(u[nb * US3 + k0 + tig]);
                bf[nt][1] = BITS(u[nb * US3 + k0 + tig + 4]);
            }
#pragma unroll
            for (int nt = 0; nt < 4; nt++)
                mma_tf32(acc[nt], af, bf[nt], acc[nt]);
        }
#pragma unroll
        for (int nt = 0; nt < 4; nt++) {
#pragma unroll
            for (int cc = 0; cc < 4; cc++) {
                int l  = warpM + g + ((cc >= 2) ? 8 : 0);
                int jc = warpN + nt * 8 + 2 * tig + (cc & 1);
                As[l * AS3 + jc] = (jc <= l) ? f2tf(acc[nt][cc]) : 0.f;
            }
        }
    }
    __syncthreads();

    // Load exclusive-prefix state S0 [128][72] over the k~ region.
    {
        const float* kvg = g_kvA + (size_t)(s * NC + c) * D2 * DIM;
        for (int i = t; i < D2 * DIM / 4; i += 256) {
            int r = i >> 4;
            int d = (i & 15) * 4;
            float4 f4 = reinterpret_cast<const float4*>(kvg)[i];
            *reinterpret_cast<float4*>(u + r * S0S + d) =
                make_float4(f2tf(f4.x), f2tf(f4.y), f2tf(f4.z), f2tf(f4.w));
        }
    }
    // Denominators.
    if (t < CHK) {
        int l = t;
        float d1 = 0.f;
#pragma unroll 8
        for (int kk = 0; kk < D2; kk++) d1 += qs[l * QS3 + kk] * ksum[kk];
        float d2v = 0.f;
        for (int jc = 0; jc <= l; jc++) d2v += As[l * AS3 + jc];
        den[l] = fmaxf(d1 + d2v, 1e-6f);
    }
    __syncthreads();

    // ---- Phase B: out = q~ @ S0 (K=128) + A @ v (K=64) ----
    float acc2[4][4];
#pragma unroll
    for (int nt = 0; nt < 4; nt++)
#pragma unroll
        for (int cc = 0; cc < 4; cc++) acc2[nt][cc] = 0.f;

#pragma unroll
    for (int kk = 0; kk < 16; kk++) {
        const int k0 = kk * 8;
        uint32_t af[4];
        af[0] = BITS(qs[(warpM + g)     * QS3 + k0 + tig]);
        af[1] = BITS(qs[(warpM + g + 8) * QS3 + k0 + tig]);
        af[2] = BITS(qs[(warpM + g)     * QS3 + k0 + tig + 4]);
        af[3] = BITS(qs[(warpM + g + 8) * QS3 + k0 + tig + 4]);
        uint32_t bf[4][2];
#pragma unroll
        for (int nt = 0; nt < 4; nt++) {
            int nb = warpN + nt * 8 + g;
            bf[nt][0] = BITS(u[(k0 + tig)     * S0S + nb]);
            bf[nt][1] = BITS(u[(k0 + tig + 4) * S0S + nb]);
        }
#pragma unroll
        for (int nt = 0; nt < 4; nt++)
            mma_tf32(acc2[nt], af, bf[nt], acc2[nt]);
    }
#pragma unroll
    for (int kk = 0; kk < 8; kk++) {
        const int k0 = kk * 8;
        uint32_t af[4];
        af[0] = BITS(As[(warpM + g)     * AS3 + k0 + tig]);
        af[1] = BITS(As[(warpM + g + 8) * AS3 + k0 + tig]);
        af[2] = BITS(As[(warpM + g)     * AS3 + k0 + tig + 4]);
        af[3] = BITS(As[(warpM + g + 8) * AS3 + k0 + tig + 4]);
        uint32_t bf[4][2];
#pragma unroll
        for (int nt = 0; nt < 4; nt++) {
            int nb = warpN + nt * 8 + g;
            bf[nt][0] = BITS(vs[(k0 + tig)     * VS3 + nb]);
            bf[nt][1] = BITS(vs[(k0 + tig + 4) * VS3 + nb]);
        }
#pragma unroll
        for (int nt = 0; nt < 4; nt++)
            mma_tf32(acc2[nt], af, bf[nt], acc2[nt]);
    }

    // Epilogue: divide by denom and store.
    float* outp = outg + (size_t)(s * LSEQ + c * CHK) * DIM;
    {
        int l0 = warpM + g;
        int l1 = l0 + 8;
        float inv0 = 1.0f / den[l0];
        float inv1 = 1.0f / den[l1];
#pragma unroll
        for (int nt = 0; nt < 4; nt++) {
            int n0 = warpN + nt * 8 + 2 * tig;
            *reinterpret_cast<float2*>(outp + l0 * DIM + n0) =
                make_float2(acc2[nt][0] * inv0, acc2[nt][1] * inv0);
            *reinterpret_cast<float2*>(outp + l1 * DIM + n0) =
                make_float2(acc2[nt][2] * inv1, acc2[nt][3] * inv1);
        }
    }
}

// ---------------------------------------------------------------------------
extern "C" void kernel_launch(void* const* d_in, const int* in_sizes, int n_in,
                              void* d_out, int out_size) {
    const float* q = (const float*)d_in[0];
    const float* k = (const float*)d_in[1];
    const float* v = (const float*)d_in[2];
    float* out = (float*)d_out;

    static bool attr_set = false;
    if (!attr_set) {
        cudaFuncSetAttribute(k_chunksum,
                             cudaFuncAttributeMaxDynamicSharedMemorySize, K1_SMEM);
        cudaFuncSetAttribute(k_output,
                             cudaFuncAttributeMaxDynamicSharedMemorySize, K3_SMEM);
        attr_set = true;
    }

    k_chunksum<<<NSEQ * NC * 2, 256, K1_SMEM>>>(k, v);
    int scan_threads = NSEQ * 2048 + NSEQ * D2;            // 34816
    k_scan<<<(scan_threads + 255) / 256, 256>>>();
    k_output<<<NSEQ * NC, 256, K3_SMEM>>>(q, k, v, out);
}

// round 8
// speedup vs baseline: 1.2222x; 1.2222x over previous
#include <cuda_runtime.h>
#include <math.h>
#include <stdint.h>

// Problem constants (B=1, H=16, L=1024, D=64)
#define NSEQ 16
#define LSEQ 1024
#define DIM  64
#define D2   128          // feature dim = 2*DIM
#define CHK  64           // chunk length
#define NC   (LSEQ/CHK)   // 16 chunks per sequence

// Scratch: per-(seq,chunk) KV sums [D2][DIM] and k-sums [D2]
__device__ float g_kv[NSEQ * NC * D2 * DIM];    // 8 MB
__device__ float g_ksum[NSEQ * NC * D2];        // 128 KB

// ---------------------------------------------------------------------------
// helpers
// ---------------------------------------------------------------------------
__device__ __forceinline__ float f2tf(float x) {
    uint32_t r;
    asm("cvt.rna.tf32.f32 %0, %1;" : "=r"(r) : "f"(x));
    return __uint_as_float(r);
}

__device__ __forceinline__ void mma_tf32(float d[4],
                                         const uint32_t a[4],
                                         const uint32_t b[2],
                                         const float c[4]) {
    asm volatile(
        "mma.sync.aligned.m16n8k8.row.col.f32.tf32.tf32.f32 "
        "{%0,%1,%2,%3}, {%4,%5,%6,%7}, {%8,%9}, {%10,%11,%12,%13};\n"
        : "=f"(d[0]), "=f"(d[1]), "=f"(d[2]), "=f"(d[3])
        : "r"(a[0]), "r"(a[1]), "r"(a[2]), "r"(a[3]),
          "r"(b[0]), "r"(b[1]),
          "f"(c[0]), "f"(c[1]), "f"(c[2]), "f"(c[3]));
}

__device__ __forceinline__ void cpa16(uint32_t smem_dst, const void* gsrc) {
    asm volatile("cp.async.cg.shared.global [%0], [%1], 16;\n"
                 :: "r"(smem_dst), "l"(gsrc));
}

#define BITS(x) __float_as_uint(x)

// ---------------------------------------------------------------------------
// Kernel 1: per-chunk KV sums via tensor cores.
// grid = NSEQ*NC = 256, 256 threads (8 warps).
// C[128(d2) x 64(dv)] = k~^T @ v over K=64 positions.
// ---------------------------------------------------------------------------
#define K1_KS 136
#define K1_VS 72
#define K1_SMEM ((CHK*K1_KS + CHK*K1_VS) * sizeof(float))

__global__ __launch_bounds__(256)
void k_chunksum(const float* __restrict__ kg_,
                const float* __restrict__ vg_) {
    extern __shared__ float sm[];
    float* ks = sm;                   // [64][136]
    float* vs = sm + CHK * K1_KS;     // [64][72]

    const int s = blockIdx.x >> 4;
    const int c = blockIdx.x & 15;
    const int t = threadIdx.x;

    const float* kg = kg_ + (size_t)(s * LSEQ + c * CHK) * DIM;
    const float* vg = vg_ + (size_t)(s * LSEQ + c * CHK) * DIM;

    // Load + feature-map k (fast sincos), load v; tf32-round.
#pragma unroll
    for (int i = t; i < CHK * DIM / 4; i += 256) {
        int j = i >> 4;
        int d = (i & 15) * 4;
        float4 k4 = reinterpret_cast<const float4*>(kg)[i];
        float4 v4 = reinterpret_cast<const float4*>(vg)[i];
        int gl = c * CHK + j;
        float w = 1.5707963267948966f * (float)(gl + 1) * (1.0f / (float)LSEQ);
        float sw, cw;
        __sincosf(w, &sw, &cw);
        float kx = fmaxf(k4.x, 0.f), ky = fmaxf(k4.y, 0.f);
        float kz = fmaxf(k4.z, 0.f), kw = fmaxf(k4.w, 0.f);
        *reinterpret_cast<float4*>(ks + j * K1_KS + d) =
            make_float4(f2tf(kx * sw), f2tf(ky * sw), f2tf(kz * sw), f2tf(kw * sw));
        *reinterpret_cast<float4*>(ks + j * K1_KS + 64 + d) =
            make_float4(f2tf(kx * cw), f2tf(ky * cw), f2tf(kz * cw), f2tf(kw * cw));
        *reinterpret_cast<float4*>(vs + j * K1_VS + d) =
            make_float4(f2tf(v4.x), f2tf(v4.y), f2tf(v4.z), f2tf(v4.w));
    }
    __syncthreads();

    const int wid  = t >> 5;
    const int lane = t & 31;
    const int g    = lane >> 2;
    const int tig  = lane & 3;
    const int warpM = (wid >> 1) * 32;   // 0,32,64,96 (d2)
    const int warpN = (wid & 1) * 32;    // 0,32 (dv)

    float acc[2][4][4];
#pragma unroll
    for (int mt = 0; mt < 2; mt++)
#pragma unroll
        for (int nt = 0; nt < 4; nt++)
#pragma unroll
            for (int cc = 0; cc < 4; cc++) acc[mt][nt][cc] = 0.f;

#pragma unroll
    for (int kk = 0; kk < 8; kk++) {
        const int k0 = kk * 8;
        uint32_t af[2][4];
#pragma unroll
        for (int mt = 0; mt < 2; mt++) {
            int mb = warpM + mt * 16 + g;
            af[mt][0] = BITS(ks[(k0 + tig)     * K1_KS + mb]);
            af[mt][1] = BITS(ks[(k0 + tig)     * K1_KS + mb + 8]);
            af[mt][2] = BITS(ks[(k0 + tig + 4) * K1_KS + mb]);
            af[mt][3] = BITS(ks[(k0 + tig + 4) * K1_KS + mb + 8]);
        }
        uint32_t bf[4][2];
#pragma unroll
        for (int nt = 0; nt < 4; nt++) {
            int nb = warpN + nt * 8 + g;
            bf[nt][0] = BITS(vs[(k0 + tig)     * K1_VS + nb]);
            bf[nt][1] = BITS(vs[(k0 + tig + 4) * K1_VS + nb]);
        }
#pragma unroll
        for (int mt = 0; mt < 2; mt++)
#pragma unroll
            for (int nt = 0; nt < 4; nt++)
                mma_tf32(acc[mt][nt], af[mt], bf[nt], acc[mt][nt]);
    }

    // Store chunk KV sum.
    float* outp = g_kv + (size_t)(s * NC + c) * D2 * DIM;
#pragma unroll
    for (int mt = 0; mt < 2; mt++)
#pragma unroll
        for (int nt = 0; nt < 4; nt++) {
            int m0 = warpM + mt * 16 + g;
            int n0 = warpN + nt * 8 + 2 * tig;
            *reinterpret_cast<float2*>(outp + m0 * DIM + n0) =
                make_float2(acc[mt][nt][0], acc[mt][nt][1]);
            *reinterpret_cast<float2*>(outp + (m0 + 8) * DIM + n0) =
                make_float2(acc[mt][nt][2], acc[mt][nt][3]);
        }

    // k-sum per feature dim.
    if (t < D2) {
        float ssum = 0.f;
#pragma unroll 8
        for (int j = 0; j < CHK; j++) ssum += ks[j * K1_KS + t];
        g_ksum[(size_t)(s * NC + c) * D2 + t] = ssum;
    }
}

// ---------------------------------------------------------------------------
// Kernel 2: exclusive prefix scan over chunks. Full 16-chunk preload per
// thread (MLP=16): one latency exposure instead of 16 serial round-trips.
// threads: 32768 (kv float4 cols) + 2048 (ksum cols) = 34816
// ---------------------------------------------------------------------------
__global__ __launch_bounds__(256)
void k_scan() {
    const int gtid = blockIdx.x * blockDim.x + threadIdx.x;
    if (gtid < NSEQ * 2048) {
        int s = gtid >> 11;
        int e = gtid & 2047;
        float4* base = reinterpret_cast<float4*>(g_kv) + (size_t)s * NC * 2048 + e;
        float4 tmp[NC];
#pragma unroll
        for (int c = 0; c < NC; c++) tmp[c] = base[(size_t)c * 2048];
        float4 run = make_float4(0.f, 0.f, 0.f, 0.f);
#pragma unroll
        for (int c = 0; c < NC; c++) {
            float4 x = tmp[c];
            base[(size_t)c * 2048] = run;
            run.x += x.x; run.y += x.y; run.z += x.z; run.w += x.w;
        }
    } else if (gtid < NSEQ * 2048 + NSEQ * D2) {
        int idx = gtid - NSEQ * 2048;
        int s = idx >> 7;
        int e = idx & 127;
        float* b2 = g_ksum + (size_t)s * NC * D2 + e;
        float tmp[NC];
#pragma unroll
        for (int c = 0; c < NC; c++) tmp[c] = b2[c * D2];
        float run = 0.f;
#pragma unroll
        for (int c = 0; c < NC; c++) {
            float x = tmp[c];
            b2[c * D2] = run;
            run += x;
        }
    }
}

// ---------------------------------------------------------------------------
// Kernel 3: per-chunk output via tensor cores. grid = NSEQ*NC, 256 threads.
// S0 prefetched with cp.async overlapped with denominator computation.
// ---------------------------------------------------------------------------
#define QS3 132
#define US3 132
#define S0S 72
#define VS3 72
#define AS3 68
#define K3_U_FLOATS 9216   /* max(64*132=8448, 128*72=9216) */
#define K3_SMEM_FLOATS (64*QS3 + K3_U_FLOATS + 64*VS3 + 64*AS3 + 128 + 64)
#define K3_SMEM (K3_SMEM_FLOATS * sizeof(float))

__global__ __launch_bounds__(256)
void k_output(const float* __restrict__ qg_,
              const float* __restrict__ kg_,
              const float* __restrict__ vg_,
              float* __restrict__ outg) {
    extern __shared__ float sm[];
    float* qs    = sm;
    float* u     = qs + 64 * QS3;        // k~ then S0
    float* vs    = u + K3_U_FLOATS;
    float* As    = vs + 64 * VS3;
    float* ksum  = As + 64 * AS3;
    float* den   = ksum + 128;

    const int s = blockIdx.x >> 4;
    const int c = blockIdx.x & 15;
    const int t = threadIdx.x;

    const float* qg = qg_ + (size_t)(s * LSEQ + c * CHK) * DIM;
    const float* kg = kg_ + (size_t)(s * LSEQ + c * CHK) * DIM;
    const float* vg = vg_ + (size_t)(s * LSEQ + c * CHK) * DIM;

#pragma unroll
    for (int i = t; i < CHK * DIM / 4; i += 256) {
        int j = i >> 4;
        int d = (i & 15) * 4;
        float4 q4 = reinterpret_cast<const float4*>(qg)[i];
        float4 k4 = reinterpret_cast<const float4*>(kg)[i];
        float4 v4 = reinterpret_cast<const float4*>(vg)[i];
        int gl = c * CHK + j;
        float w = 1.5707963267948966f * (float)(gl + 1) * (1.0f / (float)LSEQ);
        float sw, cw;
        __sincosf(w, &sw, &cw);
        float qx = fmaxf(q4.x, 0.f), qy = fmaxf(q4.y, 0.f);
        float qz = fmaxf(q4.z, 0.f), qw = fmaxf(q4.w, 0.f);
        float kx = fmaxf(k4.x, 0.f), ky = fmaxf(k4.y, 0.f);
        float kz = fmaxf(k4.z, 0.f), kw = fmaxf(k4.w, 0.f);
        *reinterpret_cast<float4*>(qs + j * QS3 + d) =
            make_float4(f2tf(qx * sw), f2tf(qy * sw), f2tf(qz * sw), f2tf(qw * sw));
        *reinterpret_cast<float4*>(qs + j * QS3 + 64 + d) =
            make_float4(f2tf(qx * cw), f2tf(qy * cw), f2tf(qz * cw), f2tf(qw * cw));
        *reinterpret_cast<float4*>(u + j * US3 + d) =
            make_float4(f2tf(kx * sw), f2tf(ky * sw), f2tf(kz * sw), f2tf(kw * sw));
        *reinterpret_cast<float4*>(u + j * US3 + 64 + d) =
            make_float4(f2tf(kx * cw), f2tf(ky * cw), f2tf(kz * cw), f2tf(kw * cw));
        *reinterpret_cast<float4*>(vs + j * VS3 + d) =
            make_float4(f2tf(v4.x), f2tf(v4.y), f2tf(v4.z), f2tf(v4.w));
    }
    if (t < D2) ksum[t] = g_ksum[(size_t)(s * NC + c) * D2 + t];
    __syncthreads();

    const int wid  = t >> 5;
    const int lane = t & 31;
    const int g    = lane >> 2;
    const int tig  = lane & 3;
    const int warpM = (wid >> 1) * 16;   // 0,16,32,48
    const int warpN = (wid & 1) * 32;    // 0,32

    // ---- Phase A: A = q~ @ k~^T, K=128 ----
    {
        float acc[4][4];
#pragma unroll
        for (int nt = 0; nt < 4; nt++)
#pragma unroll
            for (int cc = 0; cc < 4; cc++) acc[nt][cc] = 0.f;

#pragma unroll
        for (int kk = 0; kk < 16; kk++) {
            const int k0 = kk * 8;
            uint32_t af[4];
            af[0] = BITS(qs[(warpM + g)     * QS3 + k0 + tig]);
            af[1] = BITS(qs[(warpM + g + 8) * QS3 + k0 + tig]);
            af[2] = BITS(qs[(warpM + g)     * QS3 + k0 + tig + 4]);
            af[3] = BITS(qs[(warpM + g + 8) * QS3 + k0 + tig + 4]);
            uint32_t bf[4][2];
#pragma unroll
            for (int nt = 0; nt < 4; nt++) {
                int nb = warpN + nt * 8 + g;
                bf[nt][0] = BITS(u[nb * US3 + k0 + tig]);
                bf[nt][1] = BITS(u[nb * US3 + k0 + tig + 4]);
            }
#pragma unroll
            for (int nt = 0; nt < 4; nt++)
                mma_tf32(acc[nt], af, bf[nt], acc[nt]);
        }
#pragma unroll
        for (int nt = 0; nt < 4; nt++) {
#pragma unroll
            for (int cc = 0; cc < 4; cc++) {
                int l  = warpM + g + ((cc >= 2) ? 8 : 0);
                int jc = warpN + nt * 8 + 2 * tig + (cc & 1);
                As[l * AS3 + jc] = (jc <= l) ? f2tf(acc[nt][cc]) : 0.f;
            }
        }
    }
    __syncthreads();   // k~ region now dead; A_s valid

    // ---- Prefetch S0 [128][72] into u via cp.async (overlap with denom) ----
    {
        const float4* kvg = reinterpret_cast<const float4*>(
            g_kv + (size_t)(s * NC + c) * D2 * DIM);
        uint32_t ubase = (uint32_t)__cvta_generic_to_shared(u);
#pragma unroll
        for (int i = t; i < D2 * DIM / 4; i += 256) {
            int r = i >> 4;
            int d = (i & 15) * 4;
            cpa16(ubase + (r * S0S + d) * 4, kvg + i);
        }
        asm volatile("cp.async.commit_group;\n" ::: "memory");
    }

    // Denominators (uses qs, ksum, As — disjoint from the in-flight S0 copy).
    if (t < CHK) {
        int l = t;
        float d1 = 0.f;
#pragma unroll 8
        for (int kk = 0; kk < D2; kk++) d1 += qs[l * QS3 + kk] * ksum[kk];
        float d2v = 0.f;
        for (int jc = 0; jc <= l; jc++) d2v += As[l * AS3 + jc];
        den[l] = fmaxf(d1 + d2v, 1e-6f);
    }
    asm volatile("cp.async.wait_group 0;\n" ::: "memory");
    __syncthreads();

    // ---- Phase B: out = q~ @ S0 (K=128) + A @ v (K=64) ----
    float acc2[4][4];
#pragma unroll
    for (int nt = 0; nt < 4; nt++)
#pragma unroll
        for (int cc = 0; cc < 4; cc++) acc2[nt][cc] = 0.f;

#pragma unroll
    for (int kk = 0; kk < 16; kk++) {
        const int k0 = kk * 8;
        uint32_t af[4];
        af[0] = BITS(qs[(warpM + g)     * QS3 + k0 + tig]);
        af[1] = BITS(qs[(warpM + g + 8) * QS3 + k0 + tig]);
        af[2] = BITS(qs[(warpM + g)     * QS3 + k0 + tig + 4]);
        af[3] = BITS(qs[(warpM + g + 8) * QS3 + k0 + tig + 4]);
        uint32_t bf[4][2];
#pragma unroll
        for (int nt = 0; nt < 4; nt++) {
            int nb = warpN + nt * 8 + g;
            bf[nt][0] = BITS(u[(k0 + tig)     * S0S + nb]);
            bf[nt][1] = BITS(u[(k0 + tig + 4) * S0S + nb]);
        }
#pragma unroll
        for (int nt = 0; nt < 4; nt++)
            mma_tf32(acc2[nt], af, bf[nt], acc2[nt]);
    }
#pragma unroll
    for (int kk = 0; kk < 8; kk++) {
        const int k0 = kk * 8;
        uint32_t af[4];
        af[0] = BITS(As[(warpM + g)     * AS3 + k0 + tig]);
        af[1] = BITS(As[(warpM + g + 8) * AS3 + k0 + tig]);
        af[2] = BITS(As[(warpM + g)     * AS3 + k0 + tig + 4]);
        af[3] = BITS(As[(warpM + g + 8) * AS3 + k0 + tig + 4]);
        uint32_t bf[4][2];
#pragma unroll
        for (int nt = 0; nt < 4; nt++) {
            int nb = warpN + nt * 8 + g;
            bf[nt][0] = BITS(vs[(k0 + tig)     * VS3 + nb]);
            bf[nt][1] = BITS(vs[(k0 + tig + 4) * VS3 + nb]);
        }
#pragma unroll
        for (int nt = 0; nt < 4; nt++)
            mma_tf32(acc2[nt], af, bf[nt], acc2[nt]);
    }

    // Epilogue: divide by denom and store.
    float* outp = outg + (size_t)(s * LSEQ + c * CHK) * DIM;
    {
        int l0 = warpM + g;
        int l1 = l0 + 8;
        float inv0 = 1.0f / den[l0];
        float inv1 = 1.0f / den[l1];
#pragma unroll
        for (int nt = 0; nt < 4; nt++) {
            int n0 = warpN + nt * 8 + 2 * tig;
            *reinterpret_cast<float2*>(outp + l0 * DIM + n0) =
                make_float2(acc2[nt][0] * inv0, acc2[nt][1] * inv0);
            *reinterpret_cast<float2*>(outp + l1 * DIM + n0) =
                make_float2(acc2[nt][2] * inv1, acc2[nt][3] * inv1);
        }
    }
}

// ---------------------------------------------------------------------------
extern "C" void kernel_launch(void* const* d_in, const int* in_sizes, int n_in,
                              void* d_out, int out_size) {
    const float* q = (const float*)d_in[0];
    const float* k = (const float*)d_in[1];
    const float* v = (const float*)d_in[2];
    float* out = (float*)d_out;

    static bool attr_set = false;
    if (!attr_set) {
        cudaFuncSetAttribute(k_chunksum,
                             cudaFuncAttributeMaxDynamicSharedMemorySize, K1_SMEM);
        cudaFuncSetAttribute(k_output,
                             cudaFuncAttributeMaxDynamicSharedMemorySize, K3_SMEM);
        attr_set = true;
    }

    k_chunksum<<<NSEQ * NC, 256, K1_SMEM>>>(k, v);
    int scan_threads = NSEQ * 2048 + NSEQ * D2;            // 34816
    k_scan<<<(scan_threads + 255) / 256, 256>>>();
    k_output<<<NSEQ * NC, 256, K3_SMEM>>>(q, k, v, out);
}